// round 7
// baseline (speedup 1.0000x reference)
#include <cuda_runtime.h>
#include <math.h>
#include <stdint.h>

#define HID 128
#define EB  64          // rows (edges/nodes) per tile
#define STR 132         // padded smem row stride (floats) -> conflict-free A frags
#define KC  32          // K-chunk per MMA sweep
#define TPB 128         // 4 warps; each warp owns a 16-row band
#define PGRID 296       // persistent grid: 2 blocks x 148 SMs

// scratch: m_i segment sum, per-node A = h@W1a, B = h@W1b
__device__ float g_mi[6500000];
__device__ float g_A[6500000];
__device__ float g_B[6500000];

__global__ void zero_mi_kernel(int n4) {
    int i = blockIdx.x * blockDim.x + threadIdx.x;
    if (i < n4) ((float4*)g_mi)[i] = make_float4(0.f, 0.f, 0.f, 0.f);
}

__device__ __forceinline__ float silu_f(float v) {
    return v / (1.f + __expf(-v));
}

__device__ __forceinline__ void red_add_v4(float* addr, float a, float b, float c, float d) {
    asm volatile("red.global.add.v4.f32 [%0], {%1, %2, %3, %4};"
                 :: "l"(addr), "f"(a), "f"(b), "f"(c), "f"(d) : "memory");
}

__device__ __forceinline__ uint32_t f2tf(float v) {
    uint32_t t;
    asm("cvt.rna.tf32.f32 %0, %1;" : "=r"(t) : "f"(v));
    return t;
}

__device__ __forceinline__ void mma_tf32(float* c,
                                         uint32_t a0, uint32_t a1, uint32_t a2, uint32_t a3,
                                         uint32_t b0, uint32_t b1) {
    asm volatile("mma.sync.aligned.m16n8k8.row.col.f32.tf32.tf32.f32 "
                 "{%0,%1,%2,%3}, {%4,%5,%6,%7}, {%8,%9}, {%0,%1,%2,%3};"
                 : "+f"(c[0]), "+f"(c[1]), "+f"(c[2]), "+f"(c[3])
                 : "r"(a0), "r"(a1), "r"(a2), "r"(a3), "r"(b0), "r"(b1));
}

// stage nrows x HID fp32 weights into smem as tf32, XOR-swizzled (bank-conflict-free B frags)
__device__ __forceinline__ void stage_w(uint32_t* ws, const float* __restrict__ wsrc,
                                        int tid, int nrows) {
    for (int i = tid; i < nrows * HID; i += TPB) {
        int r = i >> 7, c = i & 127;
        ws[(r << 7) + (c ^ ((r & 3) << 3))] = f2tf(wsrc[i]);
    }
}

// warp computes acc[16 n-tiles][4] += Act[rowbase..+16, kcol0..+KC) @ Wchunk (ws = chunk base)
__device__ __forceinline__ void warp_mma_chunk(const float* __restrict__ act, int rowbase,
                                               int kcol0, const uint32_t* __restrict__ ws,
                                               float acc[16][4], int lane) {
    const int m = lane & 3, q = lane >> 2;
    #pragma unroll
    for (int kk = 0; kk < KC; kk += 8) {
        const float* ar0 = act + (rowbase + q) * STR + kcol0 + kk + m;
        uint32_t a0 = f2tf(ar0[0]);
        uint32_t a1 = f2tf(ar0[8 * STR]);
        uint32_t a2 = f2tf(ar0[4]);
        uint32_t a3 = f2tf(ar0[8 * STR + 4]);
        const uint32_t* w0 = ws + (kk + m) * HID;
        const int sw = m << 3;
        #pragma unroll
        for (int j = 0; j < 16; ++j) {
            uint32_t b0 = w0[(j * 8 + q) ^ sw];
            uint32_t b1 = w0[4 * HID + ((j * 8 + q) ^ sw)];
            mma_tf32(acc[j], a0, a1, a2, a3, b0, b1);
        }
    }
}

// ---------------------------------------------------------------------------
// Pre kernel (persistent): A = h @ W1a (phase 0), B = h @ W1b (phase 1).
// Full 128x128 weight resident per phase; tiles looped.
// ---------------------------------------------------------------------------
__global__ void __launch_bounds__(TPB, 2)
pre_kernel(const float* __restrict__ h, const float* __restrict__ w1, int N) {
    extern __shared__ float sm[];
    float* ha = sm;                                // EB*STR
    uint32_t* ws = (uint32_t*)(ha + EB * STR);     // HID*HID

    const int tid = threadIdx.x;
    const int lane = tid & 31, warp = tid >> 5;
    const int rowbase = warp * 16;
    const int m = lane & 3, q = lane >> 2;
    const int ntiles = (N + EB - 1) / EB;

    for (int half = 0; half < 2; ++half) {
        __syncthreads();   // prior-phase MMA reads of ws complete
        stage_w(ws, w1 + (long)half * HID * HID, tid, HID);
        __syncthreads();

        float* dst = half ? g_B : g_A;
        for (int tile = blockIdx.x; tile < ntiles; tile += gridDim.x) {
            const long nbase = (long)tile * EB;
            for (int i = tid; i < EB * 32; i += TPB) {
                int row = i >> 5, c4 = i & 31;
                long n = nbase + row;
                float4 v = make_float4(0.f, 0.f, 0.f, 0.f);
                if (n < (long)N) v = ((const float4*)(h + n * HID))[c4];
                ((float4*)(ha + row * STR))[c4] = v;
            }
            __syncthreads();

            float acc[16][4];
            #pragma unroll
            for (int j = 0; j < 16; ++j)
                #pragma unroll
                for (int t = 0; t < 4; ++t) acc[j][t] = 0.f;

            #pragma unroll
            for (int kb = 0; kb < 4; ++kb)
                warp_mma_chunk(ha, rowbase, kb * KC, ws + kb * KC * HID, acc, lane);

            long r0 = nbase + rowbase + q;
            long r1 = r0 + 8;
            #pragma unroll
            for (int j = 0; j < 16; ++j) {
                int col = j * 8 + 2 * m;
                if (r0 < (long)N) {
                    dst[r0 * HID + col]     = acc[j][0];
                    dst[r0 * HID + col + 1] = acc[j][1];
                }
                if (r1 < (long)N) {
                    dst[r1 * HID + col]     = acc[j][2];
                    dst[r1 * HID + col + 1] = acc[j][3];
                }
            }
            __syncthreads();   // all warps done reading ha before next tile overwrites
        }
    }
}

// ---------------------------------------------------------------------------
// Edge kernel (persistent): w2 fully resident; per tile:
//   gather hs = silu(A[s]+B[t]+d*w1d+b1)  (fused)
//   m2 = silu(hs @ w2 + b2)               (tf32 MMA, no staging)
//   g  = sigmoid(m2 . winf + binf)
//   g_mi[s] += g * m2                     (red.v4)
// ---------------------------------------------------------------------------
__global__ void __launch_bounds__(TPB, 2)
edge_kernel(const float* __restrict__ x, const int* __restrict__ edges,
            const float* __restrict__ w1, const float* __restrict__ b1,
            const float* __restrict__ w2, const float* __restrict__ b2,
            const float* __restrict__ winf, const float* __restrict__ binf,
            int N, int E) {
    extern __shared__ float sm[];
    float* hs = sm;                                 // EB*STR : m1 -> m2
    uint32_t* ws = (uint32_t*)(hs + EB * STR);      // HID*HID (w2 resident)
    float* s_wi  = (float*)(ws + HID * HID);        // HID
    float* s_b2  = s_wi + HID;                      // HID
    float* s_w1d = s_b2 + HID;                      // HID
    float* s_b1  = s_w1d + HID;                     // HID
    float* s_gd  = s_b1 + HID;                      // EB : dist
    float* s_g   = s_gd + EB;                       // EB : gate
    int*   s_st  = (int*)(s_g + EB);                // EB
    int*   s_en  = s_st + EB;                       // EB

    const int tid = threadIdx.x;
    const int lane = tid & 31, warp = tid >> 5;
    const int rowbase = warp * 16;
    const int m = lane & 3, q = lane >> 2;
    const int ntiles = (E + EB - 1) / EB;
    const float bi = binf[0];

    if (tid < HID) {
        s_wi[tid]  = winf[tid];
        s_b2[tid]  = b2[tid];
        s_w1d[tid] = w1[256 * HID + tid];
        s_b1[tid]  = b1[tid];
    }
    stage_w(ws, w2, tid, HID);
    __syncthreads();

    for (int tile = blockIdx.x; tile < ntiles; tile += gridDim.x) {
        const long ebase = (long)tile * EB;

        if (tid < EB) {
            long e = ebase + tid;
            int st = -1, en = -1; float d = 0.f;
            if (e < (long)E) {
                st = edges[2 * e];
                en = edges[2 * e + 1];
                float dx = x[3 * st + 0] - x[3 * en + 0];
                float dy = x[3 * st + 1] - x[3 * en + 1];
                float dz = x[3 * st + 2] - x[3 * en + 2];
                d = sqrtf(dx * dx + dy * dy + dz * dz);
            }
            s_st[tid] = st; s_en[tid] = en; s_gd[tid] = d;
        }
        __syncthreads();

        // gather fused with m1 = silu(A[s]+B[t] + d*w1d + b1)
        for (int i = tid; i < EB * 32; i += TPB) {
            int row = i >> 5, c4 = i & 31;
            int rs = s_st[row], rt = s_en[row];
            float4 v = make_float4(0.f, 0.f, 0.f, 0.f);
            if (rs >= 0) {
                float4 a = ((const float4*)(g_A + (long)rs * HID))[c4];
                float4 b = ((const float4*)(g_B + (long)rt * HID))[c4];
                float d = s_gd[row];
                int col = c4 * 4;
                v.x = silu_f(fmaf(d, s_w1d[col + 0], a.x + b.x) + s_b1[col + 0]);
                v.y = silu_f(fmaf(d, s_w1d[col + 1], a.y + b.y) + s_b1[col + 1]);
                v.z = silu_f(fmaf(d, s_w1d[col + 2], a.z + b.z) + s_b1[col + 2]);
                v.w = silu_f(fmaf(d, s_w1d[col + 3], a.w + b.w) + s_b1[col + 3]);
            }
            ((float4*)(hs + row * STR))[c4] = v;
        }
        __syncthreads();

        // m2 = m1 @ w2  (resident weights, no per-chunk syncs)
        float acc[16][4];
        #pragma unroll
        for (int j = 0; j < 16; ++j)
            #pragma unroll
            for (int t = 0; t < 4; ++t) acc[j][t] = 0.f;

        #pragma unroll
        for (int kb = 0; kb < 4; ++kb)
            warp_mma_chunk(hs, rowbase, kb * KC, ws + kb * KC * HID, acc, lane);

        // bias + silu + gate partial dot in fragments
        float p0 = 0.f, p1 = 0.f;
        #pragma unroll
        for (int j = 0; j < 16; ++j) {
            int col = j * 8 + 2 * m;
            float b0v = s_b2[col], b1v = s_b2[col + 1];
            acc[j][0] = silu_f(acc[j][0] + b0v);
            acc[j][1] = silu_f(acc[j][1] + b1v);
            acc[j][2] = silu_f(acc[j][2] + b0v);
            acc[j][3] = silu_f(acc[j][3] + b1v);
            float w0v = s_wi[col], w1v = s_wi[col + 1];
            p0 = fmaf(acc[j][0], w0v, fmaf(acc[j][1], w1v, p0));
            p1 = fmaf(acc[j][2], w0v, fmaf(acc[j][3], w1v, p1));
        }
        p0 += __shfl_xor_sync(0xffffffffu, p0, 1);
        p0 += __shfl_xor_sync(0xffffffffu, p0, 2);
        p1 += __shfl_xor_sync(0xffffffffu, p1, 1);
        p1 += __shfl_xor_sync(0xffffffffu, p1, 2);
        if (m == 0) {
            s_g[rowbase + q]     = 1.f / (1.f + __expf(-(p0 + bi)));
            s_g[rowbase + q + 8] = 1.f / (1.f + __expf(-(p1 + bi)));
        }

        // store m2 fragments back to hs (own warp band only)
        #pragma unroll
        for (int j = 0; j < 16; ++j) {
            int col = j * 8 + 2 * m;
            float* r0 = hs + (rowbase + q) * STR + col;
            r0[0] = acc[j][0];
            r0[1] = acc[j][1];
            r0[8 * STR]     = acc[j][2];
            r0[8 * STR + 1] = acc[j][3];
        }
        __syncthreads();

        // scatter: g_mi[src] += g * m2 ; 2 threads per row, 64 cols each
        {
            int row = tid >> 1, hc = (tid & 1) * 64;
            int st = s_st[row];
            if (st >= 0) {
                float g = s_g[row];
                const float4* srcr = (const float4*)(hs + row * STR + hc);
                float* dst = g_mi + (long)st * HID + hc;
                #pragma unroll
                for (int c4 = 0; c4 < 16; ++c4) {
                    float4 v = srcr[c4];
                    red_add_v4(dst + c4 * 4, g * v.x, g * v.y, g * v.z, g * v.w);
                }
            }
        }
        __syncthreads();   // scatter reads of hs/s_* done before next tile
    }
}

// ---------------------------------------------------------------------------
// Node kernel: h_new = h + (silu([h|m_i] @ wh1 + bh1) @ wh2 + bh2)
// One 64xSTR buffer reused: h -> m_i -> u1.  (per-chunk staging)
// ---------------------------------------------------------------------------
__global__ void __launch_bounds__(TPB, 4)
node_kernel(const float* __restrict__ h,
            const float* __restrict__ wh1, const float* __restrict__ bh1,
            const float* __restrict__ wh2, const float* __restrict__ bh2,
            float* __restrict__ out, int N) {
    extern __shared__ float sm[];
    float* ha = sm;                                 // EB*STR
    uint32_t* ws = (uint32_t*)(ha + EB * STR);      // KC*HID
    float* s_b1 = (float*)(ws + KC * HID);          // HID
    float* s_b2 = s_b1 + HID;                       // HID

    const int tid = threadIdx.x;
    const int lane = tid & 31, warp = tid >> 5;
    const int rowbase = warp * 16;
    const int m = lane & 3, q = lane >> 2;
    const long nbase = (long)blockIdx.x * EB;

    if (tid < HID) { s_b1[tid] = bh1[tid]; s_b2[tid] = bh2[tid]; }

    for (int i = tid; i < EB * 32; i += TPB) {
        int row = i >> 5, c4 = i & 31;
        long n = nbase + row;
        float4 v = make_float4(0.f, 0.f, 0.f, 0.f);
        if (n < (long)N) v = ((const float4*)(h + n * HID))[c4];
        ((float4*)(ha + row * STR))[c4] = v;
    }
    __syncthreads();

    float acc[16][4];
    #pragma unroll
    for (int j = 0; j < 16; ++j)
        #pragma unroll
        for (int t = 0; t < 4; ++t) acc[j][t] = 0.f;

    for (int kb = 0; kb < 4; ++kb) {
        stage_w(ws, wh1 + kb * KC * HID, tid, KC);
        __syncthreads();
        warp_mma_chunk(ha, rowbase, kb * KC, ws, acc, lane);
        __syncthreads();
    }
    for (int i = tid; i < EB * 32; i += TPB) {
        int row = i >> 5, c4 = i & 31;
        long n = nbase + row;
        float4 v = make_float4(0.f, 0.f, 0.f, 0.f);
        if (n < (long)N) v = ((const float4*)(g_mi + n * HID))[c4];
        ((float4*)(ha + row * STR))[c4] = v;
    }
    __syncthreads();
    for (int kb = 4; kb < 8; ++kb) {
        stage_w(ws, wh1 + kb * KC * HID, tid, KC);
        __syncthreads();
        warp_mma_chunk(ha, rowbase, (kb - 4) * KC, ws, acc, lane);
        __syncthreads();
    }

    #pragma unroll
    for (int j = 0; j < 16; ++j) {
        int col = j * 8 + 2 * m;
        float b0v = s_b1[col], b1v = s_b1[col + 1];
        float* r0 = ha + (rowbase + q) * STR + col;
        r0[0] = silu_f(acc[j][0] + b0v);
        r0[1] = silu_f(acc[j][1] + b1v);
        r0[8 * STR]     = silu_f(acc[j][2] + b0v);
        r0[8 * STR + 1] = silu_f(acc[j][3] + b1v);
    }

    float acc2[16][4];
    #pragma unroll
    for (int j = 0; j < 16; ++j)
        #pragma unroll
        for (int t = 0; t < 4; ++t) acc2[j][t] = 0.f;

    for (int kb = 0; kb < 4; ++kb) {
        stage_w(ws, wh2 + kb * KC * HID, tid, KC);
        __syncthreads();
        warp_mma_chunk(ha, rowbase, kb * KC, ws, acc2, lane);
        __syncthreads();
    }

    long r0 = nbase + rowbase + q;
    long r1 = r0 + 8;
    #pragma unroll
    for (int j = 0; j < 16; ++j) {
        int col = j * 8 + 2 * m;
        float b0v = s_b2[col], b1v = s_b2[col + 1];
        if (r0 < (long)N) {
            const float* hr = h + r0 * HID + col;
            float* orow = out + r0 * HID + col;
            orow[0] = hr[0] + acc2[j][0] + b0v;
            orow[1] = hr[1] + acc2[j][1] + b1v;
        }
        if (r1 < (long)N) {
            const float* hr = h + r1 * HID + col;
            float* orow = out + r1 * HID + col;
            orow[0] = hr[0] + acc2[j][2] + b0v;
            orow[1] = hr[1] + acc2[j][3] + b1v;
        }
    }
}

extern "C" void kernel_launch(void* const* d_in, const int* in_sizes, int n_in,
                              void* d_out, int out_size) {
    const float* h     = (const float*)d_in[0];
    const float* x     = (const float*)d_in[1];
    const int*   edges = (const int*)d_in[2];
    const float* w_e1  = (const float*)d_in[3];
    const float* b_e1  = (const float*)d_in[4];
    const float* w_e2  = (const float*)d_in[5];
    const float* b_e2  = (const float*)d_in[6];
    const float* w_inf = (const float*)d_in[7];
    const float* b_inf = (const float*)d_in[8];
    const float* w_h1  = (const float*)d_in[9];
    const float* b_h1  = (const float*)d_in[10];
    const float* w_h2  = (const float*)d_in[11];
    const float* b_h2  = (const float*)d_in[12];
    float* out = (float*)d_out;

    int N = in_sizes[0] / HID;
    int E = in_sizes[2] / 2;

    const int SMEM_P = (EB * STR + HID * HID) * 4;
    const int SMEM_E = (EB * STR + HID * HID + 4 * HID + 4 * EB) * 4;
    const int SMEM_N = (EB * STR + KC * HID + 2 * HID) * 4;
    cudaFuncSetAttribute(pre_kernel,  cudaFuncAttributeMaxDynamicSharedMemorySize, SMEM_P);
    cudaFuncSetAttribute(edge_kernel, cudaFuncAttributeMaxDynamicSharedMemorySize, SMEM_E);
    cudaFuncSetAttribute(node_kernel, cudaFuncAttributeMaxDynamicSharedMemorySize, SMEM_N);

    int n4 = (N * HID) / 4;
    zero_mi_kernel<<<(n4 + 255) / 256, 256>>>(n4);

    int ptiles = (N + EB - 1) / EB;
    int etiles = (E + EB - 1) / EB;
    int pgrid = ptiles < PGRID ? ptiles : PGRID;
    int egrid = etiles < PGRID ? etiles : PGRID;

    pre_kernel<<<pgrid, TPB, SMEM_P>>>(h, w_e1, N);

    edge_kernel<<<egrid, TPB, SMEM_E>>>(
        x, edges, w_e1, b_e1, w_e2, b_e2, w_inf, b_inf, N, E);

    node_kernel<<<(N + EB - 1) / EB, TPB, SMEM_N>>>(
        h, w_h1, b_h1, w_h2, b_h2, out, N);
}

// round 9
// speedup vs baseline: 1.0868x; 1.0868x over previous
#include <cuda_runtime.h>
#include <math.h>
#include <stdint.h>

#define HID 128
#define STR 132         // padded band row stride (floats) -> conflict-free A frags
#define TPB 128         // 4 warps per block; each warp owns 16 rows independently
#define WB  16          // rows per warp

// scratch: m_i segment sum, per-node A = h@W1a, B = h@W1b
__device__ float g_mi[6500000];
__device__ float g_A[6500000];
__device__ float g_B[6500000];
// tf32 pre-converted weights
__device__ uint32_t g_w1tf[32768];   // w_e1 rows 0..255 (both halves)
__device__ uint32_t g_w2tf[16384];   // w_e2
__device__ uint32_t g_wh1tf[32768];  // w_h1 (256x128)
__device__ uint32_t g_wh2tf[16384];  // w_h2

__global__ void zero_mi_kernel(int n4) {
    int i = blockIdx.x * blockDim.x + threadIdx.x;
    if (i < n4) ((float4*)g_mi)[i] = make_float4(0.f, 0.f, 0.f, 0.f);
}

__device__ __forceinline__ uint32_t f2tf(float v) {
    uint32_t t;
    asm("cvt.rna.tf32.f32 %0, %1;" : "=r"(t) : "f"(v));
    return t;
}

// one-shot weight conversion fp32 -> tf32 (global scratch)
__global__ void conv_w_kernel(const float* __restrict__ we1, const float* __restrict__ we2,
                              const float* __restrict__ wh1, const float* __restrict__ wh2) {
    int i = blockIdx.x * blockDim.x + threadIdx.x;
    if (i < 32768)                       g_w1tf[i]           = f2tf(we1[i]);
    else if (i < 32768 + 16384)          g_w2tf[i - 32768]   = f2tf(we2[i - 32768]);
    else if (i < 32768 + 16384 + 32768)  g_wh1tf[i - 49152]  = f2tf(wh1[i - 49152]);
    else if (i < 98304)                  g_wh2tf[i - 81920]  = f2tf(wh2[i - 81920]);
}

__device__ __forceinline__ float silu_f(float v) {
    return v / (1.f + __expf(-v));
}

__device__ __forceinline__ void red_add_v2(float* addr, float a, float b) {
    asm volatile("red.global.add.v2.f32 [%0], {%1, %2};"
                 :: "l"(addr), "f"(a), "f"(b) : "memory");
}

__device__ __forceinline__ void mma_tf32(float* c,
                                         uint32_t a0, uint32_t a1, uint32_t a2, uint32_t a3,
                                         uint32_t b0, uint32_t b1) {
    asm volatile("mma.sync.aligned.m16n8k8.row.col.f32.tf32.tf32.f32 "
                 "{%0,%1,%2,%3}, {%4,%5,%6,%7}, {%8,%9}, {%0,%1,%2,%3};"
                 : "+f"(c[0]), "+f"(c[1]), "+f"(c[2]), "+f"(c[3])
                 : "r"(a0), "r"(a1), "r"(a2), "r"(a3), "r"(b0), "r"(b1));
}

// warp-local: acc[16][4] += band[16 x 128] @ Wtf[128 x 128]
// A from smem band (fp32, converted on the fly), B via __ldg from tf32 global (L1-hot).
__device__ __forceinline__ void warp_mma_g(const float* __restrict__ band,
                                           const uint32_t* __restrict__ wtf,
                                           float acc[16][4], int lane) {
    const int m = lane & 3, q = lane >> 2;
    #pragma unroll
    for (int kk = 0; kk < HID; kk += 8) {
        const float* ar0 = band + q * STR + kk + m;
        uint32_t a0 = f2tf(ar0[0]);
        uint32_t a1 = f2tf(ar0[8 * STR]);
        uint32_t a2 = f2tf(ar0[4]);
        uint32_t a3 = f2tf(ar0[8 * STR + 4]);
        const uint32_t* w0 = wtf + (kk + m) * HID + q;
        #pragma unroll
        for (int j = 0; j < 16; ++j) {
            uint32_t b0 = __ldg(w0 + j * 8);
            uint32_t b1 = __ldg(w0 + 4 * HID + j * 8);
            mma_tf32(acc[j], a0, a1, a2, a3, b0, b1);
        }
    }
}

// ---------------------------------------------------------------------------
// Pre kernel: A = h @ W1a, B = h @ W1b. Fully warp-independent.
// ---------------------------------------------------------------------------
__global__ void __launch_bounds__(TPB)
pre_kernel(const float* __restrict__ h, int N) {
    extern __shared__ float sm[];
    const int tid = threadIdx.x;
    const int lane = tid & 31, warp = tid >> 5;
    float* band = sm + warp * WB * STR;
    const int m = lane & 3, q = lane >> 2;
    const long nbase = (long)blockIdx.x * 64 + warp * WB;

    // load own 16 rows of h
    for (int k = 0; k < WB; ++k) {
        long n = nbase + k;
        float4 v = make_float4(0.f, 0.f, 0.f, 0.f);
        if (n < (long)N) v = __ldg((const float4*)(h + n * HID) + lane);
        ((float4*)(band + k * STR))[lane] = v;
    }
    __syncwarp();

    long r0 = nbase + q, r1 = r0 + 8;

    for (int half = 0; half < 2; ++half) {
        float acc[16][4];
        #pragma unroll
        for (int j = 0; j < 16; ++j)
            #pragma unroll
            for (int t = 0; t < 4; ++t) acc[j][t] = 0.f;

        warp_mma_g(band, g_w1tf + half * 16384, acc, lane);

        float* dst = half ? g_B : g_A;
        #pragma unroll
        for (int j = 0; j < 16; ++j) {
            int col = j * 8 + 2 * m;
            if (r0 < (long)N) *(float2*)(dst + r0 * HID + col) = make_float2(acc[j][0], acc[j][1]);
            if (r1 < (long)N) *(float2*)(dst + r1 * HID + col) = make_float2(acc[j][2], acc[j][3]);
        }
    }
}

// ---------------------------------------------------------------------------
// Edge kernel: fully warp-independent; 16 edges per warp.
//   m1 = silu(A[s]+B[t]+d*w1d+b1)  fused into gather
//   m2 = silu(m1 @ w2 + b2)        tf32 MMA, B from global tf32
//   g  = sigmoid(m2 . winf + binf) fragment dot + quad shfl
//   g_mi[s] += g*m2                red.v2 straight from fragments
// ---------------------------------------------------------------------------
__global__ void __launch_bounds__(TPB)
edge_kernel(const float* __restrict__ x, const int* __restrict__ edges,
            const float* __restrict__ w1, const float* __restrict__ b1,
            const float* __restrict__ b2,
            const float* __restrict__ winf, const float* __restrict__ binf,
            int E) {
    extern __shared__ float sm[];
    const int tid = threadIdx.x;
    const int lane = tid & 31, warp = tid >> 5;
    float* band = sm + warp * WB * STR;
    const int m = lane & 3, q = lane >> 2;
    const long ebase = (long)blockIdx.x * 64 + warp * WB;

    // lanes 0..15 own one edge each: indices + distance
    int st = -1, en = 0;
    float d = 0.f;
    if (lane < WB) {
        long e = ebase + lane;
        if (e < (long)E) {
            st = edges[2 * e];
            en = edges[2 * e + 1];
            float dx = __ldg(x + 3 * st + 0) - __ldg(x + 3 * en + 0);
            float dy = __ldg(x + 3 * st + 1) - __ldg(x + 3 * en + 1);
            float dz = __ldg(x + 3 * st + 2) - __ldg(x + 3 * en + 2);
            d = sqrtf(dx * dx + dy * dy + dz * dz);
        }
    }

    // per-lane column params (c4 = lane fixed)
    float4 w1d4 = __ldg((const float4*)(w1 + 256 * HID) + lane);
    float4 b14  = __ldg((const float4*)b1 + lane);
    __syncwarp();

    // gather own 16 rows, fused m1 = silu(A[s]+B[t]+d*w1d+b1)
    for (int k = 0; k < WB; ++k) {
        int rs  = __shfl_sync(0xffffffffu, st, k);
        int rt  = __shfl_sync(0xffffffffu, en, k);
        float dd = __shfl_sync(0xffffffffu, d, k);
        float4 v = make_float4(0.f, 0.f, 0.f, 0.f);
        if (rs >= 0) {
            float4 a = __ldg((const float4*)(g_A + (long)rs * HID) + lane);
            float4 b = __ldg((const float4*)(g_B + (long)rt * HID) + lane);
            v.x = silu_f(fmaf(dd, w1d4.x, a.x + b.x) + b14.x);
            v.y = silu_f(fmaf(dd, w1d4.y, a.y + b.y) + b14.y);
            v.z = silu_f(fmaf(dd, w1d4.z, a.z + b.z) + b14.z);
            v.w = silu_f(fmaf(dd, w1d4.w, a.w + b.w) + b14.w);
        }
        ((float4*)(band + k * STR))[lane] = v;
    }
    __syncwarp();

    // m2 = m1 @ w2
    float acc[16][4];
    #pragma unroll
    for (int j = 0; j < 16; ++j)
        #pragma unroll
        for (int t = 0; t < 4; ++t) acc[j][t] = 0.f;

    warp_mma_g(band, g_w2tf, acc, lane);

    // bias + silu + gate partial dot
    float p0 = 0.f, p1 = 0.f;
    #pragma unroll
    for (int j = 0; j < 16; ++j) {
        int col = j * 8 + 2 * m;
        float b0v = __ldg(b2 + col), b1v = __ldg(b2 + col + 1);
        acc[j][0] = silu_f(acc[j][0] + b0v);
        acc[j][1] = silu_f(acc[j][1] + b1v);
        acc[j][2] = silu_f(acc[j][2] + b0v);
        acc[j][3] = silu_f(acc[j][3] + b1v);
        float w0v = __ldg(winf + col), w1v = __ldg(winf + col + 1);
        p0 = fmaf(acc[j][0], w0v, fmaf(acc[j][1], w1v, p0));
        p1 = fmaf(acc[j][2], w0v, fmaf(acc[j][3], w1v, p1));
    }
    p0 += __shfl_xor_sync(0xffffffffu, p0, 1);
    p0 += __shfl_xor_sync(0xffffffffu, p0, 2);
    p1 += __shfl_xor_sync(0xffffffffu, p1, 1);
    p1 += __shfl_xor_sync(0xffffffffu, p1, 2);
    float bi = __ldg(binf);
    float g0 = 1.f / (1.f + __expf(-(p0 + bi)));
    float g1 = 1.f / (1.f + __expf(-(p1 + bi)));

    // scatter from fragments: rows q and q+8
    int st0 = __shfl_sync(0xffffffffu, st, q);
    int st1 = __shfl_sync(0xffffffffu, st, q + 8);
    if (st0 >= 0) {
        float* dst = g_mi + (long)st0 * HID + 2 * m;
        #pragma unroll
        for (int j = 0; j < 16; ++j)
            red_add_v2(dst + j * 8, g0 * acc[j][0], g0 * acc[j][1]);
    }
    if (st1 >= 0) {
        float* dst = g_mi + (long)st1 * HID + 2 * m;
        #pragma unroll
        for (int j = 0; j < 16; ++j)
            red_add_v2(dst + j * 8, g1 * acc[j][2], g1 * acc[j][3]);
    }
}

// ---------------------------------------------------------------------------
// Node kernel: h_new = h + (silu([h|m_i] @ wh1 + bh1) @ wh2 + bh2)
// Fully warp-independent; band reused h -> m_i -> u1.
// ---------------------------------------------------------------------------
__global__ void __launch_bounds__(TPB)
node_kernel(const float* __restrict__ h,
            const float* __restrict__ bh1, const float* __restrict__ bh2,
            float* __restrict__ out, int N) {
    extern __shared__ float sm[];
    const int tid = threadIdx.x;
    const int lane = tid & 31, warp = tid >> 5;
    float* band = sm + warp * WB * STR;
    const int m = lane & 3, q = lane >> 2;
    const long nbase = (long)blockIdx.x * 64 + warp * WB;

    // h rows
    for (int k = 0; k < WB; ++k) {
        long n = nbase + k;
        float4 v = make_float4(0.f, 0.f, 0.f, 0.f);
        if (n < (long)N) v = __ldg((const float4*)(h + n * HID) + lane);
        ((float4*)(band + k * STR))[lane] = v;
    }
    __syncwarp();

    float acc[16][4];
    #pragma unroll
    for (int j = 0; j < 16; ++j)
        #pragma unroll
        for (int t = 0; t < 4; ++t) acc[j][t] = 0.f;

    warp_mma_g(band, g_wh1tf, acc, lane);          // K-part from h
    __syncwarp();

    // m_i rows
    for (int k = 0; k < WB; ++k) {
        long n = nbase + k;
        float4 v = make_float4(0.f, 0.f, 0.f, 0.f);
        if (n < (long)N) v = ((const float4*)(g_mi + n * HID))[lane];
        ((float4*)(band + k * STR))[lane] = v;
    }
    __syncwarp();

    warp_mma_g(band, g_wh1tf + 16384, acc, lane);  // K-part from m_i (accumulate)
    __syncwarp();

    // u1 = silu(acc + bh1) -> band (each lane writes its fragment cells)
    #pragma unroll
    for (int j = 0; j < 16; ++j) {
        int col = j * 8 + 2 * m;
        float b0v = __ldg(bh1 + col), b1v = __ldg(bh1 + col + 1);
        *(float2*)(band + q * STR + col) =
            make_float2(silu_f(acc[j][0] + b0v), silu_f(acc[j][1] + b1v));
        *(float2*)(band + (q + 8) * STR + col) =
            make_float2(silu_f(acc[j][2] + b0v), silu_f(acc[j][3] + b1v));
    }
    __syncwarp();

    float acc2[16][4];
    #pragma unroll
    for (int j = 0; j < 16; ++j)
        #pragma unroll
        for (int t = 0; t < 4; ++t) acc2[j][t] = 0.f;

    warp_mma_g(band, g_wh2tf, acc2, lane);

    long r0 = nbase + q, r1 = r0 + 8;
    #pragma unroll
    for (int j = 0; j < 16; ++j) {
        int col = j * 8 + 2 * m;
        float b0v = __ldg(bh2 + col), b1v = __ldg(bh2 + col + 1);
        if (r0 < (long)N) {
            float2 hv = *(const float2*)(h + r0 * HID + col);
            *(float2*)(out + r0 * HID + col) =
                make_float2(hv.x + acc2[j][0] + b0v, hv.y + acc2[j][1] + b1v);
        }
        if (r1 < (long)N) {
            float2 hv = *(const float2*)(h + r1 * HID + col);
            *(float2*)(out + r1 * HID + col) =
                make_float2(hv.x + acc2[j][2] + b0v, hv.y + acc2[j][3] + b1v);
        }
    }
}

extern "C" void kernel_launch(void* const* d_in, const int* in_sizes, int n_in,
                              void* d_out, int out_size) {
    const float* h     = (const float*)d_in[0];
    const float* x     = (const float*)d_in[1];
    const int*   edges = (const int*)d_in[2];
    const float* w_e1  = (const float*)d_in[3];
    const float* b_e1  = (const float*)d_in[4];
    const float* w_e2  = (const float*)d_in[5];
    const float* b_e2  = (const float*)d_in[6];
    const float* w_inf = (const float*)d_in[7];
    const float* b_inf = (const float*)d_in[8];
    const float* w_h1  = (const float*)d_in[9];
    const float* b_h1  = (const float*)d_in[10];
    const float* w_h2  = (const float*)d_in[11];
    const float* b_h2  = (const float*)d_in[12];
    float* out = (float*)d_out;

    int N = in_sizes[0] / HID;
    int E = in_sizes[2] / 2;

    const int SMEM = 64 * STR * 4;   // 33792 B: one 16xSTR band per warp

    int n4 = (N * HID) / 4;
    zero_mi_kernel<<<(n4 + 255) / 256, 256>>>(n4);
    conv_w_kernel<<<(98304 + 255) / 256, 256>>>(w_e1, w_e2, w_h1, w_h2);

    pre_kernel<<<(N + 63) / 64, TPB, SMEM>>>(h, N);

    edge_kernel<<<(E + 63) / 64, TPB, SMEM>>>(
        x, edges, w_e1, b_e1, b_e2, w_inf, b_inf, E);

    node_kernel<<<(N + 63) / 64, TPB, SMEM>>>(
        h, b_h1, b_h2, out, N);
}

// round 10
// speedup vs baseline: 1.5059x; 1.3856x over previous
#include <cuda_runtime.h>
#include <math.h>
#include <stdint.h>

#define HID 128
#define STR 132         // padded band row stride (floats) -> conflict-free A frags
#define TPB 128         // 4 warps per block; each warp owns 16 rows independently
#define WB  16          // rows per warp

// scratch: m_i segment sum, per-node A = h@W1a, B = h@W1b
__device__ float g_mi[6500000];
__device__ float g_A[6500000];
__device__ float g_B[6500000];
// fragment-packed tf32 weights: 6 matrices x 4096 uint4
// mats: 0=w_e1a 1=w_e1b 2=w_e2 3=w_h1a 4=w_h1b 5=w_h2
__device__ uint4 g_wpk[24576];

__global__ void zero_mi_kernel(int n4) {
    int i = blockIdx.x * blockDim.x + threadIdx.x;
    if (i < n4) ((float4*)g_mi)[i] = make_float4(0.f, 0.f, 0.f, 0.f);
}

__device__ __forceinline__ uint32_t f2tf(float v) {
    uint32_t t;
    asm("cvt.rna.tf32.f32 %0, %1;" : "=r"(t) : "f"(v));
    return t;
}

// one-shot pack: W[128][128] fp32 -> fragment-ordered tf32 uint4s.
// index i: mat = i>>12; r=i&4095; kkidx=r>>8; jp=(r>>5)&7; lane=r&31; m=lane&3; q=lane>>2
// value lanes need for MMA (kk=8*kkidx, cols 16*jp..+15):
//   {W[kk+m][16jp+q], W[kk+4+m][16jp+q], W[kk+m][16jp+8+q], W[kk+4+m][16jp+8+q]}
__global__ void pack_w_kernel(const float* __restrict__ we1, const float* __restrict__ we2,
                              const float* __restrict__ wh1, const float* __restrict__ wh2) {
    int i = blockIdx.x * blockDim.x + threadIdx.x;
    if (i >= 24576) return;
    int mat = i >> 12;
    int r = i & 4095;
    int kkidx = r >> 8, jp = (r >> 5) & 7, lane = r & 31;
    int m = lane & 3, q = lane >> 2;
    const float* src;
    switch (mat) {
        case 0: src = we1;          break;
        case 1: src = we1 + 16384;  break;
        case 2: src = we2;          break;
        case 3: src = wh1;          break;
        case 4: src = wh1 + 16384;  break;
        default: src = wh2;         break;
    }
    int k0 = kkidx * 8 + m, c0 = jp * 16 + q;
    uint4 v;
    v.x = f2tf(src[k0 * HID + c0]);
    v.y = f2tf(src[(k0 + 4) * HID + c0]);
    v.z = f2tf(src[k0 * HID + c0 + 8]);
    v.w = f2tf(src[(k0 + 4) * HID + c0 + 8]);
    g_wpk[i] = v;
}

__device__ __forceinline__ float silu_f(float v) {
    return v / (1.f + __expf(-v));
}

__device__ __forceinline__ void red_add_v2(float* addr, float a, float b) {
    asm volatile("red.global.add.v2.f32 [%0], {%1, %2};"
                 :: "l"(addr), "f"(a), "f"(b) : "memory");
}

__device__ __forceinline__ void mma_tf32(float* c,
                                         uint32_t a0, uint32_t a1, uint32_t a2, uint32_t a3,
                                         uint32_t b0, uint32_t b1) {
    asm volatile("mma.sync.aligned.m16n8k8.row.col.f32.tf32.tf32.f32 "
                 "{%0,%1,%2,%3}, {%4,%5,%6,%7}, {%8,%9}, {%0,%1,%2,%3};"
                 : "+f"(c[0]), "+f"(c[1]), "+f"(c[2]), "+f"(c[3])
                 : "r"(a0), "r"(a1), "r"(a2), "r"(a3), "r"(b0), "r"(b1));
}

// warp-local: acc[16][4] += band[16 x 128] @ W (fragment-packed).
// A from smem band (fp32 -> tf32 on the fly), B via coalesced LDG.128.
__device__ __forceinline__ void warp_mma_p(const float* __restrict__ band,
                                           const uint4* __restrict__ wp,
                                           float acc[16][4], int lane) {
    const int m = lane & 3, q = lane >> 2;
    #pragma unroll
    for (int kkidx = 0; kkidx < 16; ++kkidx) {
        const float* ar0 = band + q * STR + kkidx * 8 + m;
        uint32_t a0 = f2tf(ar0[0]);
        uint32_t a1 = f2tf(ar0[8 * STR]);
        uint32_t a2 = f2tf(ar0[4]);
        uint32_t a3 = f2tf(ar0[8 * STR + 4]);
        const uint4* w0 = wp + kkidx * 256 + lane;
        #pragma unroll
        for (int jp = 0; jp < 8; ++jp) {
            uint4 b = __ldg(w0 + jp * 32);
            mma_tf32(acc[2 * jp],     a0, a1, a2, a3, b.x, b.y);
            mma_tf32(acc[2 * jp + 1], a0, a1, a2, a3, b.z, b.w);
        }
    }
}

// ---------------------------------------------------------------------------
// Pre kernel: A = h @ W1a, B = h @ W1b. Fully warp-independent.
// ---------------------------------------------------------------------------
__global__ void __launch_bounds__(TPB)
pre_kernel(const float* __restrict__ h, int N) {
    extern __shared__ float sm[];
    const int tid = threadIdx.x;
    const int lane = tid & 31, warp = tid >> 5;
    float* band = sm + warp * WB * STR;
    const int m = lane & 3, q = lane >> 2;
    const long nbase = (long)blockIdx.x * 64 + warp * WB;

    for (int k = 0; k < WB; ++k) {
        long n = nbase + k;
        float4 v = make_float4(0.f, 0.f, 0.f, 0.f);
        if (n < (long)N) v = __ldg((const float4*)(h + n * HID) + lane);
        ((float4*)(band + k * STR))[lane] = v;
    }
    __syncwarp();

    long r0 = nbase + q, r1 = r0 + 8;

    for (int half = 0; half < 2; ++half) {
        float acc[16][4];
        #pragma unroll
        for (int j = 0; j < 16; ++j)
            #pragma unroll
            for (int t = 0; t < 4; ++t) acc[j][t] = 0.f;

        warp_mma_p(band, g_wpk + half * 4096, acc, lane);

        float* dst = half ? g_B : g_A;
        #pragma unroll
        for (int j = 0; j < 16; ++j) {
            int col = j * 8 + 2 * m;
            if (r0 < (long)N) *(float2*)(dst + r0 * HID + col) = make_float2(acc[j][0], acc[j][1]);
            if (r1 < (long)N) *(float2*)(dst + r1 * HID + col) = make_float2(acc[j][2], acc[j][3]);
        }
    }
}

// ---------------------------------------------------------------------------
// Edge kernel: fully warp-independent; 16 edges per warp.
//   m1 = silu(A[s]+B[t]+d*w1d+b1)  fused into gather
//   m2 = silu(m1 @ w2 + b2)        tf32 MMA, B fragment-packed
//   g  = sigmoid(m2 . winf + binf) fragment dot + quad shfl
//   g_mi[s] += g*m2                red.v2 straight from fragments
// ---------------------------------------------------------------------------
__global__ void __launch_bounds__(TPB)
edge_kernel(const float* __restrict__ x, const int* __restrict__ edges,
            const float* __restrict__ w1, const float* __restrict__ b1,
            const float* __restrict__ b2,
            const float* __restrict__ winf, const float* __restrict__ binf,
            int E) {
    extern __shared__ float sm[];
    const int tid = threadIdx.x;
    const int lane = tid & 31, warp = tid >> 5;
    float* band = sm + warp * WB * STR;
    const int m = lane & 3, q = lane >> 2;
    const long ebase = (long)blockIdx.x * 64 + warp * WB;

    int st = -1, en = 0;
    float d = 0.f;
    if (lane < WB) {
        long e = ebase + lane;
        if (e < (long)E) {
            st = edges[2 * e];
            en = edges[2 * e + 1];
            float dx = __ldg(x + 3 * st + 0) - __ldg(x + 3 * en + 0);
            float dy = __ldg(x + 3 * st + 1) - __ldg(x + 3 * en + 1);
            float dz = __ldg(x + 3 * st + 2) - __ldg(x + 3 * en + 2);
            d = sqrtf(dx * dx + dy * dy + dz * dz);
        }
    }

    float4 w1d4 = __ldg((const float4*)(w1 + 256 * HID) + lane);
    float4 b14  = __ldg((const float4*)b1 + lane);
    __syncwarp();

    for (int k = 0; k < WB; ++k) {
        int rs  = __shfl_sync(0xffffffffu, st, k);
        int rt  = __shfl_sync(0xffffffffu, en, k);
        float dd = __shfl_sync(0xffffffffu, d, k);
        float4 v = make_float4(0.f, 0.f, 0.f, 0.f);
        if (rs >= 0) {
            float4 a = __ldg((const float4*)(g_A + (long)rs * HID) + lane);
            float4 b = __ldg((const float4*)(g_B + (long)rt * HID) + lane);
            v.x = silu_f(fmaf(dd, w1d4.x, a.x + b.x) + b14.x);
            v.y = silu_f(fmaf(dd, w1d4.y, a.y + b.y) + b14.y);
            v.z = silu_f(fmaf(dd, w1d4.z, a.z + b.z) + b14.z);
            v.w = silu_f(fmaf(dd, w1d4.w, a.w + b.w) + b14.w);
        }
        ((float4*)(band + k * STR))[lane] = v;
    }
    __syncwarp();

    float acc[16][4];
    #pragma unroll
    for (int j = 0; j < 16; ++j)
        #pragma unroll
        for (int t = 0; t < 4; ++t) acc[j][t] = 0.f;

    warp_mma_p(band, g_wpk + 2 * 4096, acc, lane);

    float p0 = 0.f, p1 = 0.f;
    #pragma unroll
    for (int j = 0; j < 16; ++j) {
        int col = j * 8 + 2 * m;
        float b0v = __ldg(b2 + col), b1v = __ldg(b2 + col + 1);
        acc[j][0] = silu_f(acc[j][0] + b0v);
        acc[j][1] = silu_f(acc[j][1] + b1v);
        acc[j][2] = silu_f(acc[j][2] + b0v);
        acc[j][3] = silu_f(acc[j][3] + b1v);
        float w0v = __ldg(winf + col), w1v = __ldg(winf + col + 1);
        p0 = fmaf(acc[j][0], w0v, fmaf(acc[j][1], w1v, p0));
        p1 = fmaf(acc[j][2], w0v, fmaf(acc[j][3], w1v, p1));
    }
    p0 += __shfl_xor_sync(0xffffffffu, p0, 1);
    p0 += __shfl_xor_sync(0xffffffffu, p0, 2);
    p1 += __shfl_xor_sync(0xffffffffu, p1, 1);
    p1 += __shfl_xor_sync(0xffffffffu, p1, 2);
    float bi = __ldg(binf);
    float g0 = 1.f / (1.f + __expf(-(p0 + bi)));
    float g1 = 1.f / (1.f + __expf(-(p1 + bi)));

    int st0 = __shfl_sync(0xffffffffu, st, q);
    int st1 = __shfl_sync(0xffffffffu, st, q + 8);
    if (st0 >= 0) {
        float* dst = g_mi + (long)st0 * HID + 2 * m;
        #pragma unroll
        for (int j = 0; j < 16; ++j)
            red_add_v2(dst + j * 8, g0 * acc[j][0], g0 * acc[j][1]);
    }
    if (st1 >= 0) {
        float* dst = g_mi + (long)st1 * HID + 2 * m;
        #pragma unroll
        for (int j = 0; j < 16; ++j)
            red_add_v2(dst + j * 8, g1 * acc[j][2], g1 * acc[j][3]);
    }
}

// ---------------------------------------------------------------------------
// Node kernel: h_new = h + (silu([h|m_i] @ wh1 + bh1) @ wh2 + bh2)
// Fully warp-independent; band reused h -> m_i -> u1.
// ---------------------------------------------------------------------------
__global__ void __launch_bounds__(TPB)
node_kernel(const float* __restrict__ h,
            const float* __restrict__ bh1, const float* __restrict__ bh2,
            float* __restrict__ out, int N) {
    extern __shared__ float sm[];
    const int tid = threadIdx.x;
    const int lane = tid & 31, warp = tid >> 5;
    float* band = sm + warp * WB * STR;
    const int m = lane & 3, q = lane >> 2;
    const long nbase = (long)blockIdx.x * 64 + warp * WB;

    for (int k = 0; k < WB; ++k) {
        long n = nbase + k;
        float4 v = make_float4(0.f, 0.f, 0.f, 0.f);
        if (n < (long)N) v = __ldg((const float4*)(h + n * HID) + lane);
        ((float4*)(band + k * STR))[lane] = v;
    }
    __syncwarp();

    float acc[16][4];
    #pragma unroll
    for (int j = 0; j < 16; ++j)
        #pragma unroll
        for (int t = 0; t < 4; ++t) acc[j][t] = 0.f;

    warp_mma_p(band, g_wpk + 3 * 4096, acc, lane);   // K-part from h
    __syncwarp();

    for (int k = 0; k < WB; ++k) {
        long n = nbase + k;
        float4 v = make_float4(0.f, 0.f, 0.f, 0.f);
        if (n < (long)N) v = ((const float4*)(g_mi + n * HID))[lane];
        ((float4*)(band + k * STR))[lane] = v;
    }
    __syncwarp();

    warp_mma_p(band, g_wpk + 4 * 4096, acc, lane);   // K-part from m_i
    __syncwarp();

    #pragma unroll
    for (int j = 0; j < 16; ++j) {
        int col = j * 8 + 2 * m;
        float b0v = __ldg(bh1 + col), b1v = __ldg(bh1 + col + 1);
        *(float2*)(band + q * STR + col) =
            make_float2(silu_f(acc[j][0] + b0v), silu_f(acc[j][1] + b1v));
        *(float2*)(band + (q + 8) * STR + col) =
            make_float2(silu_f(acc[j][2] + b0v), silu_f(acc[j][3] + b1v));
    }
    __syncwarp();

    float acc2[16][4];
    #pragma unroll
    for (int j = 0; j < 16; ++j)
        #pragma unroll
        for (int t = 0; t < 4; ++t) acc2[j][t] = 0.f;

    warp_mma_p(band, g_wpk + 5 * 4096, acc2, lane);

    long r0 = nbase + q, r1 = r0 + 8;
    #pragma unroll
    for (int j = 0; j < 16; ++j) {
        int col = j * 8 + 2 * m;
        float b0v = __ldg(bh2 + col), b1v = __ldg(bh2 + col + 1);
        if (r0 < (long)N) {
            float2 hv = *(const float2*)(h + r0 * HID + col);
            *(float2*)(out + r0 * HID + col) =
                make_float2(hv.x + acc2[j][0] + b0v, hv.y + acc2[j][1] + b1v);
        }
        if (r1 < (long)N) {
            float2 hv = *(const float2*)(h + r1 * HID + col);
            *(float2*)(out + r1 * HID + col) =
                make_float2(hv.x + acc2[j][2] + b0v, hv.y + acc2[j][3] + b1v);
        }
    }
}

extern "C" void kernel_launch(void* const* d_in, const int* in_sizes, int n_in,
                              void* d_out, int out_size) {
    const float* h     = (const float*)d_in[0];
    const float* x     = (const float*)d_in[1];
    const int*   edges = (const int*)d_in[2];
    const float* w_e1  = (const float*)d_in[3];
    const float* b_e1  = (const float*)d_in[4];
    const float* w_e2  = (const float*)d_in[5];
    const float* b_e2  = (const float*)d_in[6];
    const float* w_inf = (const float*)d_in[7];
    const float* b_inf = (const float*)d_in[8];
    const float* w_h1  = (const float*)d_in[9];
    const float* b_h1  = (const float*)d_in[10];
    const float* w_h2  = (const float*)d_in[11];
    const float* b_h2  = (const float*)d_in[12];
    float* out = (float*)d_out;

    int N = in_sizes[0] / HID;
    int E = in_sizes[2] / 2;

    const int SMEM = 64 * STR * 4;   // 33792 B: one 16xSTR band per warp

    int n4 = (N * HID) / 4;
    zero_mi_kernel<<<(n4 + 255) / 256, 256>>>(n4);
    pack_w_kernel<<<(24576 + 255) / 256, 256>>>(w_e1, w_e2, w_h1, w_h2);

    pre_kernel<<<(N + 63) / 64, TPB, SMEM>>>(h, N);

    edge_kernel<<<(E + 63) / 64, TPB, SMEM>>>(
        x, edges, w_e1, b_e1, b_e2, w_inf, b_inf, E);

    node_kernel<<<(N + 63) / 64, TPB, SMEM>>>(
        h, b_h1, b_h2, out, N);
}